// round 15
// baseline (speedup 1.0000x reference)
#include <cuda_runtime.h>
#include <cuda_fp16.h>
#include <cstdint>

// Problem constants (fixed by the dataset)
#define N_NODES   50000
#define N_EDGES   1600000
#define N_GRAPHS  512
#define IN_SIZE   44
#define HIDDEN    256
#define CONVS     3
#define CAT       (HIDDEN * CONVS)   // 768

// ---------------- device scratch (no allocation allowed) ----------------
__device__ __align__(256) float  g_h[N_NODES * HIDDEN];    // node features fp32 (51.2 MB)
__device__ __align__(256) __half g_hb[N_NODES * HIDDEN];   // fp16 copy for neighbor gather (25.6 MB)
__device__ __align__(256) __half g_x[N_NODES * HIDDEN];    // GEMM input fp16 (25.6 MB)
__device__ __align__(256) __half g_Wh[HIDDEN * HIDDEN];    // W_lin hi
__device__ __align__(256) __half g_Wl[HIDDEN * HIDDEN];    // W_lin lo
__device__ __align__(256) int   g_csrsrc[N_EDGES];
__device__ __align__(256) int   g_deg[N_NODES];
__device__ __align__(256) float g_invdeg[N_NODES];
__device__ __align__(256) int   g_rowptr[N_NODES + 8];
__device__ __align__(256) int   g_cursor[N_NODES];
__device__ __align__(256) int   g_bsum[64];
__device__ __align__(256) int   g_boff[64];
__device__ __align__(256) int   g_gcnt[N_GRAPHS];
__device__ __align__(256) int   g_gstart[N_GRAPHS + 8];
__device__ __align__(256) float g_ginv[N_GRAPHS];
__device__ __align__(256) float g_gmean[N_GRAPHS * CAT];

static __device__ __forceinline__ int clampi(int v, int lo, int hi) {
    return v < lo ? lo : (v > hi ? hi : v);
}

// ---------------- tensor-core primitives ----------------
static __device__ __forceinline__ void ldsm4(uint32_t& r0, uint32_t& r1, uint32_t& r2, uint32_t& r3,
                                             const void* p) {
    uint32_t a = (uint32_t)__cvta_generic_to_shared(p);
    asm volatile("ldmatrix.sync.aligned.m8n8.x4.shared.b16 {%0,%1,%2,%3},[%4];"
                 : "=r"(r0), "=r"(r1), "=r"(r2), "=r"(r3) : "r"(a));
}
static __device__ __forceinline__ void ldsm4t(uint32_t& r0, uint32_t& r1, uint32_t& r2, uint32_t& r3,
                                              const void* p) {
    uint32_t a = (uint32_t)__cvta_generic_to_shared(p);
    asm volatile("ldmatrix.sync.aligned.m8n8.x4.trans.shared.b16 {%0,%1,%2,%3},[%4];"
                 : "=r"(r0), "=r"(r1), "=r"(r2), "=r"(r3) : "r"(a));
}
static __device__ __forceinline__ void mma16816(float* c, const uint32_t* a, const uint32_t* b) {
    asm volatile("mma.sync.aligned.m16n8k16.row.col.f32.f16.f16.f32 "
                 "{%0,%1,%2,%3},{%4,%5,%6,%7},{%8,%9},{%0,%1,%2,%3};"
                 : "+f"(c[0]), "+f"(c[1]), "+f"(c[2]), "+f"(c[3])
                 : "r"(a[0]), "r"(a[1]), "r"(a[2]), "r"(a[3]), "r"(b[0]), "r"(b[1]));
}

// ---------------- utility kernels ----------------
__global__ void zero_kernel(int n) {
    int i = blockIdx.x * blockDim.x + threadIdx.x;
    if (i < n)        { g_deg[i] = 0; g_cursor[i] = 0; }
    if (i < N_GRAPHS) g_gcnt[i] = 0;
}

// fused: degree histogram (over E) + graph-count histogram (over N)
__global__ void hist_all_kernel(const int* __restrict__ dst,
                                const int* __restrict__ gid, int E, int N) {
    int i = blockIdx.x * blockDim.x + threadIdx.x;
    if (i < E) {
        int d = dst[i];
        if (d >= 0 && d < N_NODES) atomicAdd(&g_deg[d], 1);
    }
    if (i < N) {
        int g = gid[i];
        if (g >= 0 && g < N_GRAPHS) atomicAdd(&g_gcnt[g], 1);
    }
}

// --- coalesced 3-pass exclusive scan of g_deg -> g_rowptr (+invdeg in pass3) ---
__global__ void scan_pass1_kernel(int n) {
    __shared__ int s[1024];
    int tid = threadIdx.x;
    int i = blockIdx.x * 1024 + tid;
    int v = (i < n) ? g_deg[i] : 0;
    s[tid] = v;
    __syncthreads();
    for (int off = 1; off < 1024; off <<= 1) {
        int t = (tid >= off) ? s[tid - off] : 0;
        __syncthreads();
        s[tid] += t;
        __syncthreads();
    }
    if (i < n) g_rowptr[i] = s[tid] - v;
    if (tid == 1023) g_bsum[blockIdx.x] = s[1023];
}
__global__ void scan_pass2_kernel(int nb, int n) {
    int run = 0;
    for (int b = 0; b < nb; b++) { g_boff[b] = run; run += g_bsum[b]; }
    g_rowptr[n] = run;
}
__global__ void scan_pass3_kernel(int n) {
    int i = blockIdx.x * 1024 + threadIdx.x;
    if (i < n) {
        g_rowptr[i] += g_boff[blockIdx.x];
        int d = g_deg[i];
        g_invdeg[i] = d > 0 ? 1.0f / (float)d : 0.0f;
    }
}

// exclusive scan of g_gcnt -> g_gstart, plus inverse counts.
__global__ void scan_graphs_kernel() {
    __shared__ int s[N_GRAPHS];
    int tid = threadIdx.x;
    int v = g_gcnt[tid];
    s[tid] = v;
    __syncthreads();
    for (int off = 1; off < N_GRAPHS; off <<= 1) {
        int t = (tid >= off) ? s[tid - off] : 0;
        __syncthreads();
        s[tid] += t;
        __syncthreads();
    }
    g_gstart[tid] = s[tid] - v;
    g_ginv[tid] = v > 0 ? 1.0f / (float)v : 1.0f;
    if (tid == N_GRAPHS - 1) g_gstart[N_GRAPHS] = s[tid];
}

__global__ void scatter_kernel(const int* __restrict__ src,
                               const int* __restrict__ dst, int E) {
    int e = blockIdx.x * blockDim.x + threadIdx.x;
    if (e < E) {
        int d = dst[e];
        if (d >= 0 && d < N_NODES) {
            int pos = atomicAdd(&g_cursor[d], 1);
            int idx = clampi(g_rowptr[d] + pos, 0, E - 1);
            g_csrsrc[idx] = clampi(src[e], 0, N_NODES - 1);
        }
    }
}

// split W_lin into fp16 hi/lo
__global__ void splitW_kernel(const float* __restrict__ W, int n) {
    int i = blockIdx.x * blockDim.x + threadIdx.x;
    if (i < n) {
        float w = W[i];
        __half h = __float2half_rn(w);
        g_Wh[i] = h;
        g_Wl[i] = __float2half_rn(w - __half2float(h));
    }
}

// ---------------- initial projection: g_h = h_in @ W_proj + b_proj (+ fp16 copy) ----------------
__global__ void proj_kernel(const float* __restrict__ h_in,
                            const float* __restrict__ W,
                            const float* __restrict__ b,
                            int N) {
    __shared__ float sh[8][IN_SIZE];
    int r0 = blockIdx.x * 8;
    int tid = threadIdx.x;
    for (int i = tid; i < 8 * IN_SIZE; i += blockDim.x) {
        int r = i / IN_SIZE, c = i % IN_SIZE;
        sh[r][c] = (r0 + r < N) ? h_in[(size_t)(r0 + r) * IN_SIZE + c] : 0.0f;
    }
    __syncthreads();
    int c = tid;
    float acc[8];
    float bc = b[c];
#pragma unroll
    for (int r = 0; r < 8; r++) acc[r] = bc;
    for (int k = 0; k < IN_SIZE; k++) {
        float w = W[k * HIDDEN + c];
#pragma unroll
        for (int r = 0; r < 8; r++) acc[r] = fmaf(sh[r][k], w, acc[r]);
    }
#pragma unroll
    for (int r = 0; r < 8; r++) {
        if (r0 + r < N) {
            g_h[(size_t)(r0 + r) * HIDDEN + c] = acc[r];
            g_hb[(size_t)(r0 + r) * HIDDEN + c] = __float2half_rn(acc[r]);
        }
    }
}

// ---------------- aggregation: x[v] = h[v] + invdeg[v] * sum of fp16 neighbor rows ----------
// warp per node; lane handles 8 contiguous columns = one uint4 (8 fp16) per neighbor.
// Unrolled x4 with two accumulator banks to raise MLP toward the L2 bandwidth floor.
__global__ void agg_kernel(int N, int E) {
    int node = (blockIdx.x * blockDim.x + threadIdx.x) >> 5;
    if (node >= N) return;
    int lane = threadIdx.x & 31;
    int beg = clampi(g_rowptr[node], 0, E);
    int end = clampi(g_rowptr[node + 1], beg, E);
    float a0[8] = {0.f, 0.f, 0.f, 0.f, 0.f, 0.f, 0.f, 0.f};
    float a1[8] = {0.f, 0.f, 0.f, 0.f, 0.f, 0.f, 0.f, 0.f};
    size_t coff = (size_t)lane * 8;
    int e = beg;
    for (; e + 3 < end; e += 4) {
        int u0 = g_csrsrc[e],     u1 = g_csrsrc[e + 1];
        int u2 = g_csrsrc[e + 2], u3 = g_csrsrc[e + 3];
        uint4 q0 = *(const uint4*)(g_hb + (size_t)u0 * HIDDEN + coff);
        uint4 q1 = *(const uint4*)(g_hb + (size_t)u1 * HIDDEN + coff);
        uint4 q2 = *(const uint4*)(g_hb + (size_t)u2 * HIDDEN + coff);
        uint4 q3 = *(const uint4*)(g_hb + (size_t)u3 * HIDDEN + coff);
        const __half2* p0 = (const __half2*)&q0;
        const __half2* p1 = (const __half2*)&q1;
        const __half2* p2 = (const __half2*)&q2;
        const __half2* p3 = (const __half2*)&q3;
#pragma unroll
        for (int j = 0; j < 4; j++) {
            float2 f0 = __half22float2(p0[j]);
            float2 f1 = __half22float2(p1[j]);
            float2 f2 = __half22float2(p2[j]);
            float2 f3 = __half22float2(p3[j]);
            a0[j * 2 + 0] += f0.x + f1.x;
            a0[j * 2 + 1] += f0.y + f1.y;
            a1[j * 2 + 0] += f2.x + f3.x;
            a1[j * 2 + 1] += f2.y + f3.y;
        }
    }
    for (; e < end; e++) {
        int u0 = g_csrsrc[e];
        uint4 q0 = *(const uint4*)(g_hb + (size_t)u0 * HIDDEN + coff);
        const __half2* p0 = (const __half2*)&q0;
#pragma unroll
        for (int j = 0; j < 4; j++) {
            float2 f0 = __half22float2(p0[j]);
            a0[j * 2 + 0] += f0.x;
            a0[j * 2 + 1] += f0.y;
        }
    }
    float s = g_invdeg[node];
    const float4* hv = (const float4*)(g_h + (size_t)node * HIDDEN);
    float4 h0 = hv[lane * 2], h1 = hv[lane * 2 + 1];
    float o[8];
    o[0] = h0.x + s * (a0[0] + a1[0]); o[1] = h0.y + s * (a0[1] + a1[1]);
    o[2] = h0.z + s * (a0[2] + a1[2]); o[3] = h0.w + s * (a0[3] + a1[3]);
    o[4] = h1.x + s * (a0[4] + a1[4]); o[5] = h1.y + s * (a0[5] + a1[5]);
    o[6] = h1.z + s * (a0[6] + a1[6]); o[7] = h1.w + s * (a0[7] + a1[7]);
    __half hi[8];
#pragma unroll
    for (int j = 0; j < 8; j++) hi[j] = __float2half_rn(o[j]);
    *(uint4*)(g_x + (size_t)node * HIDDEN + coff) = *(uint4*)hi;
}

// ---------------- layer GEMM (tensor cores): g_h = x @ W_lin + b_lin ----------------
// A plain fp16; W split hi/lo: C = A*Bh + A*Bl (fp32 accumulate).
// Block tile 128(M) x 64(N), BK=32, 8 warps (4M x 2N), warp tile 32x32.
// Double-buffered static smem (38.9 KB).
#define GA_STRIDE 40   // A smem row stride in fp16 (80B = 5 chunks, coprime 8)
#define GB_STRIDE 72   // B smem row stride in fp16 (144B = 9 chunks, coprime 8)
#define ASZ (128 * GA_STRIDE)
#define BSZ (32 * GB_STRIDE)
__global__ __launch_bounds__(256) void gemm_mma_kernel(const float* __restrict__ bias, int M) {
    __shared__ __align__(16) __half sA[2][ASZ];
    __shared__ __align__(16) __half sBh[2][BSZ];
    __shared__ __align__(16) __half sBl[2][BSZ];

    int tid = threadIdx.x;
    int warp = tid >> 5, lane = tid & 31;
    int m0 = blockIdx.x * 128;
    int n0 = blockIdx.y * 64;
    int wm = (warp & 3) * 32;
    int wn = (warp >> 2) * 32;

    float acc[2][4][4];
#pragma unroll
    for (int i = 0; i < 2; i++)
#pragma unroll
        for (int j = 0; j < 4; j++)
#pragma unroll
            for (int q = 0; q < 4; q++) acc[i][j][q] = 0.f;

    int aRow = tid >> 1;
    int aCh0 = (tid & 1);
    int aCh1 = (tid & 1) + 2;
    int bRow = tid >> 3, bCh = tid & 7;
    int gr = m0 + aRow;
    bool aval = (gr < M);

    uint4 pA0, pA1, pBh, pBl;
    const uint4 z4 = make_uint4(0, 0, 0, 0);

    // prologue: chunk 0 -> regs -> stage 0
    pA0 = aval ? *(const uint4*)(g_x + (size_t)gr * HIDDEN + aCh0 * 8) : z4;
    pA1 = aval ? *(const uint4*)(g_x + (size_t)gr * HIDDEN + aCh1 * 8) : z4;
    pBh = *(const uint4*)(g_Wh + (size_t)bRow * HIDDEN + n0 + bCh * 8);
    pBl = *(const uint4*)(g_Wl + (size_t)bRow * HIDDEN + n0 + bCh * 8);
    *(uint4*)(&sA[0][aRow * GA_STRIDE + aCh0 * 8]) = pA0;
    *(uint4*)(&sA[0][aRow * GA_STRIDE + aCh1 * 8]) = pA1;
    *(uint4*)(&sBh[0][bRow * GB_STRIDE + bCh * 8]) = pBh;
    *(uint4*)(&sBl[0][bRow * GB_STRIDE + bCh * 8]) = pBl;
    __syncthreads();

#pragma unroll
    for (int ck = 0; ck < HIDDEN / 32; ck++) {
        int cur = ck & 1;
        bool hasNext = (ck < HIDDEN / 32 - 1);
        if (hasNext) {
            int kn = (ck + 1) * 32;
            pA0 = aval ? *(const uint4*)(g_x + (size_t)gr * HIDDEN + kn + aCh0 * 8) : z4;
            pA1 = aval ? *(const uint4*)(g_x + (size_t)gr * HIDDEN + kn + aCh1 * 8) : z4;
            pBh = *(const uint4*)(g_Wh + (size_t)(kn + bRow) * HIDDEN + n0 + bCh * 8);
            pBl = *(const uint4*)(g_Wl + (size_t)(kn + bRow) * HIDDEN + n0 + bCh * 8);
        }

        const __half* cA = sA[cur];
        const __half* cBh = sBh[cur];
        const __half* cBl = sBl[cur];
#pragma unroll
        for (int ks = 0; ks < 2; ks++) {
            uint32_t av[2][4];
            uint32_t bh[4][2], bl[4][2];
#pragma unroll
            for (int fm = 0; fm < 2; fm++) {
                const __half* pa = cA + (wm + fm * 16 + (lane & 15)) * GA_STRIDE
                                 + ks * 16 + (lane >> 4) * 8;
                ldsm4(av[fm][0], av[fm][1], av[fm][2], av[fm][3], pa);
            }
#pragma unroll
            for (int nf = 0; nf < 2; nf++) {
                const __half* pb = cBh + (ks * 16 + (lane & 15)) * GB_STRIDE
                                 + wn + nf * 16 + (lane >> 4) * 8;
                uint32_t t0, t1, t2, t3;
                ldsm4t(t0, t1, t2, t3, pb);
                bh[nf * 2][0] = t0; bh[nf * 2][1] = t1;
                bh[nf * 2 + 1][0] = t2; bh[nf * 2 + 1][1] = t3;
                const __half* pbl = cBl + (ks * 16 + (lane & 15)) * GB_STRIDE
                                  + wn + nf * 16 + (lane >> 4) * 8;
                ldsm4t(t0, t1, t2, t3, pbl);
                bl[nf * 2][0] = t0; bl[nf * 2][1] = t1;
                bl[nf * 2 + 1][0] = t2; bl[nf * 2 + 1][1] = t3;
            }
#pragma unroll
            for (int fm = 0; fm < 2; fm++)
#pragma unroll
                for (int fn = 0; fn < 4; fn++) {
                    mma16816(acc[fm][fn], av[fm], bh[fn]);
                    mma16816(acc[fm][fn], av[fm], bl[fn]);
                }
        }

        if (hasNext) {
            int nxt = 1 - cur;
            *(uint4*)(&sA[nxt][aRow * GA_STRIDE + aCh0 * 8]) = pA0;
            *(uint4*)(&sA[nxt][aRow * GA_STRIDE + aCh1 * 8]) = pA1;
            *(uint4*)(&sBh[nxt][bRow * GB_STRIDE + bCh * 8]) = pBh;
            *(uint4*)(&sBl[nxt][bRow * GB_STRIDE + bCh * 8]) = pBl;
        }
        __syncthreads();
    }

    // epilogue: acc -> g_h fp32 and g_hb fp16 (+bias)
#pragma unroll
    for (int fm = 0; fm < 2; fm++)
#pragma unroll
        for (int fn = 0; fn < 4; fn++) {
            int col = n0 + wn + fn * 8 + (lane & 3) * 2;
            float b0 = bias[col], b1 = bias[col + 1];
            int r0 = m0 + wm + fm * 16 + (lane >> 2);
            if (r0 < M) {
                float v0 = acc[fm][fn][0] + b0, v1 = acc[fm][fn][1] + b1;
                *(float2*)(g_h + (size_t)r0 * HIDDEN + col) = make_float2(v0, v1);
                *(__half2*)(g_hb + (size_t)r0 * HIDDEN + col) = __float22half2_rn(make_float2(v0, v1));
            }
            int r1 = r0 + 8;
            if (r1 < M) {
                float v0 = acc[fm][fn][2] + b0, v1 = acc[fm][fn][3] + b1;
                *(float2*)(g_h + (size_t)r1 * HIDDEN + col) = make_float2(v0, v1);
                *(__half2*)(g_hb + (size_t)r1 * HIDDEN + col) = __float22half2_rn(make_float2(v0, v1));
            }
        }
}

// ---------------- per-graph mean of current g_h -> g_gmean[:, l*256 .. ] ----------------
__global__ void readout_layer_kernel(int l, int N) {
    int g = blockIdx.x;
    int c = threadIdx.x;
    int beg = clampi(g_gstart[g], 0, N);
    int end = clampi(g_gstart[g + 1], beg, N);
    float a = 0.f;
    for (int r = beg; r < end; r++)
        a += g_h[(size_t)r * HIDDEN + c];
    g_gmean[(size_t)g * CAT + l * HIDDEN + c] = a * g_ginv[g];
}

// ---------------- final tiny GEMM: out[512,256] = g_gmean @ W_out + b_out ----------------
__global__ void gemm_out_kernel(const float* __restrict__ W,
                                const float* __restrict__ b,
                                float* __restrict__ out) {
    __shared__ float sa[8][CAT];
    int g0 = blockIdx.x * 8;
    int tid = threadIdx.x;
    for (int i = tid; i < 8 * CAT; i += blockDim.x) {
        int r = i / CAT, k = i % CAT;
        sa[r][k] = g_gmean[(size_t)(g0 + r) * CAT + k];
    }
    __syncthreads();
    int c = tid;
    float acc[8];
    float bc = b[c];
#pragma unroll
    for (int r = 0; r < 8; r++) acc[r] = bc;
    for (int k = 0; k < CAT; k++) {
        float w = W[k * HIDDEN + c];
#pragma unroll
        for (int r = 0; r < 8; r++) acc[r] = fmaf(sa[r][k], w, acc[r]);
    }
#pragma unroll
    for (int r = 0; r < 8; r++)
        out[(size_t)(g0 + r) * HIDDEN + c] = acc[r];
}

// ---------------- launch ----------------
extern "C" void kernel_launch(void* const* d_in, const int* in_sizes, int n_in,
                              void* d_out, int out_size) {
    int ix_h = 0, ix_src = 1, ix_dst = 2, ix_gid = 3;
    int ix_Wp = 4, ix_bp = 5, ix_Wl = 6, ix_bl = 7, ix_Wo = 8, ix_bo = 9;

    if (n_in == 10) {
        int ih = -1, ig = -1, iwp = -1, iwl = -1, iwo = -1;
        int pair[2] = {-1, -1}; int pc = 0;
        int bias3[3] = {-1, -1, -1}; int bc = 0;
        bool ok = true;
        for (int i = 0; i < 10; i++) {
            int s = in_sizes[i];
            if      (s == N_NODES * IN_SIZE)  ih = i;
            else if (s == N_EDGES)            { if (pc < 2) pair[pc++] = i; else ok = false; }
            else if (s == N_NODES)            ig = i;
            else if (s == IN_SIZE * HIDDEN)   iwp = i;
            else if (s == HIDDEN * HIDDEN)    iwl = i;
            else if (s == CAT * HIDDEN)       iwo = i;
            else if (s == HIDDEN)             { if (bc < 3) bias3[bc++] = i; else ok = false; }
            else ok = false;
        }
        if (ok && ih >= 0 && ig >= 0 && iwp >= 0 && iwl >= 0 && iwo >= 0 && pc == 2 && bc == 3) {
            ix_h = ih; ix_src = pair[0]; ix_dst = pair[1]; ix_gid = ig;
            ix_Wp = iwp; ix_bp = bias3[0]; ix_Wl = iwl; ix_bl = bias3[1];
            ix_Wo = iwo; ix_bo = bias3[2];
        }
    }

    const float* h_in   = (const float*)d_in[ix_h];
    const int*   src    = (const int*)d_in[ix_src];
    const int*   dst    = (const int*)d_in[ix_dst];
    const int*   gid    = (const int*)d_in[ix_gid];
    const float* W_proj = (const float*)d_in[ix_Wp];
    const float* b_proj = (const float*)d_in[ix_bp];
    const float* W_lin  = (const float*)d_in[ix_Wl];
    const float* b_lin  = (const float*)d_in[ix_bl];
    const float* W_out  = (const float*)d_in[ix_Wo];
    const float* b_out  = (const float*)d_in[ix_bo];
    float* out = (float*)d_out;

    const int E = N_EDGES;
    const int N = N_NODES;
    const int SCAN_BLOCKS = (N + 1023) / 1024;

    zero_kernel<<<(N + 255) / 256, 256>>>(N);
    hist_all_kernel<<<(E + 255) / 256, 256>>>(dst, gid, E, N);
    scan_pass1_kernel<<<SCAN_BLOCKS, 1024>>>(N);
    scan_pass2_kernel<<<1, 1>>>(SCAN_BLOCKS, N);
    scan_pass3_kernel<<<SCAN_BLOCKS, 1024>>>(N);
    scan_graphs_kernel<<<1, N_GRAPHS>>>();
    scatter_kernel<<<(E + 255) / 256, 256>>>(src, dst, E);
    splitW_kernel<<<(HIDDEN * HIDDEN + 255) / 256, 256>>>(W_lin, HIDDEN * HIDDEN);
    proj_kernel<<<(N + 7) / 8, 256>>>(h_in, W_proj, b_proj, N);

    dim3 ggrid((N + 127) / 128, HIDDEN / 64);
    int agg_blocks = (N + 7) / 8;
    for (int l = 0; l < CONVS; l++) {
        agg_kernel<<<agg_blocks, 256>>>(N, E);
        gemm_mma_kernel<<<ggrid, 256>>>(b_lin, N);
        readout_layer_kernel<<<N_GRAPHS, 256>>>(l, N);
    }

    gemm_out_kernel<<<N_GRAPHS / 8, 256>>>(W_out, b_out, out);
}

// round 17
// speedup vs baseline: 1.0534x; 1.0534x over previous
#include <cuda_runtime.h>
#include <cuda_fp16.h>
#include <cstdint>

// Problem constants (fixed by the dataset)
#define N_NODES   50000
#define N_EDGES   1600000
#define N_GRAPHS  512
#define IN_SIZE   44
#define HIDDEN    256
#define CONVS     3
#define CAT       (HIDDEN * CONVS)   // 768

// ---------------- device scratch (no allocation allowed) ----------------
__device__ __align__(256) float  g_h[N_NODES * HIDDEN];    // node features fp32 (51.2 MB)
__device__ __align__(256) __half g_hb[N_NODES * HIDDEN];   // fp16 copy for neighbor gather (25.6 MB)
__device__ __align__(256) __half g_x[N_NODES * HIDDEN];    // GEMM input fp16 (25.6 MB)
__device__ __align__(256) __half g_Wh[HIDDEN * HIDDEN];    // W_lin hi
__device__ __align__(256) __half g_Wl[HIDDEN * HIDDEN];    // W_lin lo
__device__ __align__(256) int   g_csrsrc[N_EDGES];
__device__ __align__(256) int   g_deg[N_NODES];
__device__ __align__(256) float g_invdeg[N_NODES];
__device__ __align__(256) int   g_rowptr[N_NODES + 8];
__device__ __align__(256) int   g_cursor[N_NODES];
__device__ __align__(256) int   g_bsum[64];
__device__ __align__(256) int   g_boff[64];
__device__ __align__(256) int   g_gcnt[N_GRAPHS];
__device__ __align__(256) int   g_gstart[N_GRAPHS + 8];
__device__ __align__(256) float g_ginv[N_GRAPHS];
__device__ __align__(256) float g_gmean[N_GRAPHS * CAT];

static __device__ __forceinline__ int clampi(int v, int lo, int hi) {
    return v < lo ? lo : (v > hi ? hi : v);
}

// ---------------- tensor-core primitives ----------------
static __device__ __forceinline__ void ldsm4(uint32_t& r0, uint32_t& r1, uint32_t& r2, uint32_t& r3,
                                             const void* p) {
    uint32_t a = (uint32_t)__cvta_generic_to_shared(p);
    asm volatile("ldmatrix.sync.aligned.m8n8.x4.shared.b16 {%0,%1,%2,%3},[%4];"
                 : "=r"(r0), "=r"(r1), "=r"(r2), "=r"(r3) : "r"(a));
}
static __device__ __forceinline__ void ldsm4t(uint32_t& r0, uint32_t& r1, uint32_t& r2, uint32_t& r3,
                                              const void* p) {
    uint32_t a = (uint32_t)__cvta_generic_to_shared(p);
    asm volatile("ldmatrix.sync.aligned.m8n8.x4.trans.shared.b16 {%0,%1,%2,%3},[%4];"
                 : "=r"(r0), "=r"(r1), "=r"(r2), "=r"(r3) : "r"(a));
}
static __device__ __forceinline__ void mma16816(float* c, const uint32_t* a, const uint32_t* b) {
    asm volatile("mma.sync.aligned.m16n8k16.row.col.f32.f16.f16.f32 "
                 "{%0,%1,%2,%3},{%4,%5,%6,%7},{%8,%9},{%0,%1,%2,%3};"
                 : "+f"(c[0]), "+f"(c[1]), "+f"(c[2]), "+f"(c[3])
                 : "r"(a[0]), "r"(a[1]), "r"(a[2]), "r"(a[3]), "r"(b[0]), "r"(b[1]));
}

// ---------------- utility kernels ----------------
__global__ void zero_kernel(int n) {
    int i = blockIdx.x * blockDim.x + threadIdx.x;
    if (i < n)        { g_deg[i] = 0; g_cursor[i] = 0; }
    if (i < N_GRAPHS) g_gcnt[i] = 0;
}

// fused: degree histogram (over E) + graph-count histogram (over N)
__global__ void hist_all_kernel(const int* __restrict__ dst,
                                const int* __restrict__ gid, int E, int N) {
    int i = blockIdx.x * blockDim.x + threadIdx.x;
    if (i < E) {
        int d = dst[i];
        if (d >= 0 && d < N_NODES) atomicAdd(&g_deg[d], 1);
    }
    if (i < N) {
        int g = gid[i];
        if (g >= 0 && g < N_GRAPHS) atomicAdd(&g_gcnt[g], 1);
    }
}

// --- coalesced 3-pass exclusive scan of g_deg -> g_rowptr (+invdeg in pass3) ---
__global__ void scan_pass1_kernel(int n) {
    __shared__ int s[1024];
    int tid = threadIdx.x;
    int i = blockIdx.x * 1024 + tid;
    int v = (i < n) ? g_deg[i] : 0;
    s[tid] = v;
    __syncthreads();
    for (int off = 1; off < 1024; off <<= 1) {
        int t = (tid >= off) ? s[tid - off] : 0;
        __syncthreads();
        s[tid] += t;
        __syncthreads();
    }
    if (i < n) g_rowptr[i] = s[tid] - v;
    if (tid == 1023) g_bsum[blockIdx.x] = s[1023];
}

// fused middle pass: block 0 scans block-sums -> g_boff (+total); block 1 scans graph counts.
__global__ void scan_mid_kernel(int nb, int n) {
    if (blockIdx.x == 0) {
        __shared__ int s[64];
        int tid = threadIdx.x;          // 64 threads
        int v = (tid < nb) ? g_bsum[tid] : 0;
        s[tid] = v;
        __syncthreads();
        for (int off = 1; off < 64; off <<= 1) {
            int t = (tid >= off) ? s[tid - off] : 0;
            __syncthreads();
            s[tid] += t;
            __syncthreads();
        }
        if (tid < nb) g_boff[tid] = s[tid] - v;
        if (tid == 63) g_rowptr[n] = s[63];
    } else {
        __shared__ int s[N_GRAPHS];
        int tid = threadIdx.x;
        // 64 threads handle 512 graphs: sequential-chunk scan (8 per thread)
        int base = tid * 8;
        int loc[8];
        int sum = 0;
#pragma unroll
        for (int j = 0; j < 8; j++) { loc[j] = g_gcnt[base + j]; sum += loc[j]; }
        s[tid] = sum;
        __syncthreads();
        for (int off = 1; off < 64; off <<= 1) {
            int t = (tid >= off) ? s[tid - off] : 0;
            __syncthreads();
            s[tid] += t;
            __syncthreads();
        }
        int run = s[tid] - sum;
#pragma unroll
        for (int j = 0; j < 8; j++) {
            g_gstart[base + j] = run;
            g_ginv[base + j] = loc[j] > 0 ? 1.0f / (float)loc[j] : 1.0f;
            run += loc[j];
        }
        if (tid == 63) g_gstart[N_GRAPHS] = run;
    }
}

__global__ void scan_pass3_kernel(int n) {
    int i = blockIdx.x * 1024 + threadIdx.x;
    if (i < n) {
        g_rowptr[i] += g_boff[blockIdx.x];
        int d = g_deg[i];
        g_invdeg[i] = d > 0 ? 1.0f / (float)d : 0.0f;
    }
}

__global__ void scatter_kernel(const int* __restrict__ src,
                               const int* __restrict__ dst, int E) {
    int e = blockIdx.x * blockDim.x + threadIdx.x;
    if (e < E) {
        int d = dst[e];
        if (d >= 0 && d < N_NODES) {
            int pos = atomicAdd(&g_cursor[d], 1);
            int idx = clampi(g_rowptr[d] + pos, 0, E - 1);
            g_csrsrc[idx] = clampi(src[e], 0, N_NODES - 1);
        }
    }
}

// split W_lin into fp16 hi/lo
__global__ void splitW_kernel(const float* __restrict__ W, int n) {
    int i = blockIdx.x * blockDim.x + threadIdx.x;
    if (i < n) {
        float w = W[i];
        __half h = __float2half_rn(w);
        g_Wh[i] = h;
        g_Wl[i] = __float2half_rn(w - __half2float(h));
    }
}

// ---------------- initial projection: g_h = h_in @ W_proj + b_proj (+ fp16 copy) ----------------
__global__ void proj_kernel(const float* __restrict__ h_in,
                            const float* __restrict__ W,
                            const float* __restrict__ b,
                            int N) {
    __shared__ float sh[8][IN_SIZE];
    int r0 = blockIdx.x * 8;
    int tid = threadIdx.x;
    for (int i = tid; i < 8 * IN_SIZE; i += blockDim.x) {
        int r = i / IN_SIZE, c = i % IN_SIZE;
        sh[r][c] = (r0 + r < N) ? h_in[(size_t)(r0 + r) * IN_SIZE + c] : 0.0f;
    }
    __syncthreads();
    int c = tid;
    float acc[8];
    float bc = b[c];
#pragma unroll
    for (int r = 0; r < 8; r++) acc[r] = bc;
    for (int k = 0; k < IN_SIZE; k++) {
        float w = W[k * HIDDEN + c];
#pragma unroll
        for (int r = 0; r < 8; r++) acc[r] = fmaf(sh[r][k], w, acc[r]);
    }
#pragma unroll
    for (int r = 0; r < 8; r++) {
        if (r0 + r < N) {
            g_h[(size_t)(r0 + r) * HIDDEN + c] = acc[r];
            g_hb[(size_t)(r0 + r) * HIDDEN + c] = __float2half_rn(acc[r]);
        }
    }
}

// ---------------- aggregation: x[v] = h[v] + invdeg[v] * sum of fp16 neighbor rows ----------
// warp per node; lane handles 8 contiguous columns = one uint4 (8 fp16) per neighbor.
// x2 unroll — empirically the sweet spot (x4 regressed in R15).
__global__ void agg_kernel(int N, int E) {
    int node = (blockIdx.x * blockDim.x + threadIdx.x) >> 5;
    if (node >= N) return;
    int lane = threadIdx.x & 31;
    int beg = clampi(g_rowptr[node], 0, E);
    int end = clampi(g_rowptr[node + 1], beg, E);
    float a[8] = {0.f, 0.f, 0.f, 0.f, 0.f, 0.f, 0.f, 0.f};
    size_t coff = (size_t)lane * 8;
    int e = beg;
    for (; e + 1 < end; e += 2) {
        int u0 = g_csrsrc[e], u1 = g_csrsrc[e + 1];
        uint4 q0 = *(const uint4*)(g_hb + (size_t)u0 * HIDDEN + coff);
        uint4 q1 = *(const uint4*)(g_hb + (size_t)u1 * HIDDEN + coff);
        const __half2* p0 = (const __half2*)&q0;
        const __half2* p1 = (const __half2*)&q1;
#pragma unroll
        for (int j = 0; j < 4; j++) {
            float2 f0 = __half22float2(p0[j]);
            float2 f1 = __half22float2(p1[j]);
            a[j * 2 + 0] += f0.x + f1.x;
            a[j * 2 + 1] += f0.y + f1.y;
        }
    }
    if (e < end) {
        int u0 = g_csrsrc[e];
        uint4 q0 = *(const uint4*)(g_hb + (size_t)u0 * HIDDEN + coff);
        const __half2* p0 = (const __half2*)&q0;
#pragma unroll
        for (int j = 0; j < 4; j++) {
            float2 f0 = __half22float2(p0[j]);
            a[j * 2 + 0] += f0.x;
            a[j * 2 + 1] += f0.y;
        }
    }
    float s = g_invdeg[node];
    const float4* hv = (const float4*)(g_h + (size_t)node * HIDDEN);
    float4 h0 = hv[lane * 2], h1 = hv[lane * 2 + 1];
    float o[8];
    o[0] = h0.x + s * a[0]; o[1] = h0.y + s * a[1]; o[2] = h0.z + s * a[2]; o[3] = h0.w + s * a[3];
    o[4] = h1.x + s * a[4]; o[5] = h1.y + s * a[5]; o[6] = h1.z + s * a[6]; o[7] = h1.w + s * a[7];
    __half hi[8];
#pragma unroll
    for (int j = 0; j < 8; j++) hi[j] = __float2half_rn(o[j]);
    *(uint4*)(g_x + (size_t)node * HIDDEN + coff) = *(uint4*)hi;
}

// ---------------- layer GEMM (tensor cores): g_h = x @ W_lin + b_lin ----------------
// A plain fp16; W split hi/lo: C = A*Bh + A*Bl (fp32 accumulate).
// Block tile 128(M) x 64(N), BK=32, 8 warps (4M x 2N), warp tile 32x32.
// Double-buffered static smem (38.9 KB).
#define GA_STRIDE 40   // A smem row stride in fp16 (80B = 5 chunks, coprime 8)
#define GB_STRIDE 72   // B smem row stride in fp16 (144B = 9 chunks, coprime 8)
#define ASZ (128 * GA_STRIDE)
#define BSZ (32 * GB_STRIDE)
__global__ __launch_bounds__(256) void gemm_mma_kernel(const float* __restrict__ bias, int M) {
    __shared__ __align__(16) __half sA[2][ASZ];
    __shared__ __align__(16) __half sBh[2][BSZ];
    __shared__ __align__(16) __half sBl[2][BSZ];

    int tid = threadIdx.x;
    int warp = tid >> 5, lane = tid & 31;
    int m0 = blockIdx.x * 128;
    int n0 = blockIdx.y * 64;
    int wm = (warp & 3) * 32;
    int wn = (warp >> 2) * 32;

    float acc[2][4][4];
#pragma unroll
    for (int i = 0; i < 2; i++)
#pragma unroll
        for (int j = 0; j < 4; j++)
#pragma unroll
            for (int q = 0; q < 4; q++) acc[i][j][q] = 0.f;

    int aRow = tid >> 1;
    int aCh0 = (tid & 1);
    int aCh1 = (tid & 1) + 2;
    int bRow = tid >> 3, bCh = tid & 7;
    int gr = m0 + aRow;
    bool aval = (gr < M);

    uint4 pA0, pA1, pBh, pBl;
    const uint4 z4 = make_uint4(0, 0, 0, 0);

    // prologue: chunk 0 -> regs -> stage 0
    pA0 = aval ? *(const uint4*)(g_x + (size_t)gr * HIDDEN + aCh0 * 8) : z4;
    pA1 = aval ? *(const uint4*)(g_x + (size_t)gr * HIDDEN + aCh1 * 8) : z4;
    pBh = *(const uint4*)(g_Wh + (size_t)bRow * HIDDEN + n0 + bCh * 8);
    pBl = *(const uint4*)(g_Wl + (size_t)bRow * HIDDEN + n0 + bCh * 8);
    *(uint4*)(&sA[0][aRow * GA_STRIDE + aCh0 * 8]) = pA0;
    *(uint4*)(&sA[0][aRow * GA_STRIDE + aCh1 * 8]) = pA1;
    *(uint4*)(&sBh[0][bRow * GB_STRIDE + bCh * 8]) = pBh;
    *(uint4*)(&sBl[0][bRow * GB_STRIDE + bCh * 8]) = pBl;
    __syncthreads();

#pragma unroll
    for (int ck = 0; ck < HIDDEN / 32; ck++) {
        int cur = ck & 1;
        bool hasNext = (ck < HIDDEN / 32 - 1);
        if (hasNext) {
            int kn = (ck + 1) * 32;
            pA0 = aval ? *(const uint4*)(g_x + (size_t)gr * HIDDEN + kn + aCh0 * 8) : z4;
            pA1 = aval ? *(const uint4*)(g_x + (size_t)gr * HIDDEN + kn + aCh1 * 8) : z4;
            pBh = *(const uint4*)(g_Wh + (size_t)(kn + bRow) * HIDDEN + n0 + bCh * 8);
            pBl = *(const uint4*)(g_Wl + (size_t)(kn + bRow) * HIDDEN + n0 + bCh * 8);
        }

        const __half* cA = sA[cur];
        const __half* cBh = sBh[cur];
        const __half* cBl = sBl[cur];
#pragma unroll
        for (int ks = 0; ks < 2; ks++) {
            uint32_t av[2][4];
            uint32_t bh[4][2], bl[4][2];
#pragma unroll
            for (int fm = 0; fm < 2; fm++) {
                const __half* pa = cA + (wm + fm * 16 + (lane & 15)) * GA_STRIDE
                                 + ks * 16 + (lane >> 4) * 8;
                ldsm4(av[fm][0], av[fm][1], av[fm][2], av[fm][3], pa);
            }
#pragma unroll
            for (int nf = 0; nf < 2; nf++) {
                const __half* pb = cBh + (ks * 16 + (lane & 15)) * GB_STRIDE
                                 + wn + nf * 16 + (lane >> 4) * 8;
                uint32_t t0, t1, t2, t3;
                ldsm4t(t0, t1, t2, t3, pb);
                bh[nf * 2][0] = t0; bh[nf * 2][1] = t1;
                bh[nf * 2 + 1][0] = t2; bh[nf * 2 + 1][1] = t3;
                const __half* pbl = cBl + (ks * 16 + (lane & 15)) * GB_STRIDE
                                  + wn + nf * 16 + (lane >> 4) * 8;
                ldsm4t(t0, t1, t2, t3, pbl);
                bl[nf * 2][0] = t0; bl[nf * 2][1] = t1;
                bl[nf * 2 + 1][0] = t2; bl[nf * 2 + 1][1] = t3;
            }
#pragma unroll
            for (int fm = 0; fm < 2; fm++)
#pragma unroll
                for (int fn = 0; fn < 4; fn++) {
                    mma16816(acc[fm][fn], av[fm], bh[fn]);
                    mma16816(acc[fm][fn], av[fm], bl[fn]);
                }
        }

        if (hasNext) {
            int nxt = 1 - cur;
            *(uint4*)(&sA[nxt][aRow * GA_STRIDE + aCh0 * 8]) = pA0;
            *(uint4*)(&sA[nxt][aRow * GA_STRIDE + aCh1 * 8]) = pA1;
            *(uint4*)(&sBh[nxt][bRow * GB_STRIDE + bCh * 8]) = pBh;
            *(uint4*)(&sBl[nxt][bRow * GB_STRIDE + bCh * 8]) = pBl;
        }
        __syncthreads();
    }

    // epilogue: acc -> g_h fp32 and g_hb fp16 (+bias)
#pragma unroll
    for (int fm = 0; fm < 2; fm++)
#pragma unroll
        for (int fn = 0; fn < 4; fn++) {
            int col = n0 + wn + fn * 8 + (lane & 3) * 2;
            float b0 = bias[col], b1 = bias[col + 1];
            int r0 = m0 + wm + fm * 16 + (lane >> 2);
            if (r0 < M) {
                float v0 = acc[fm][fn][0] + b0, v1 = acc[fm][fn][1] + b1;
                *(float2*)(g_h + (size_t)r0 * HIDDEN + col) = make_float2(v0, v1);
                *(__half2*)(g_hb + (size_t)r0 * HIDDEN + col) = __float22half2_rn(make_float2(v0, v1));
            }
            int r1 = r0 + 8;
            if (r1 < M) {
                float v0 = acc[fm][fn][2] + b0, v1 = acc[fm][fn][3] + b1;
                *(float2*)(g_h + (size_t)r1 * HIDDEN + col) = make_float2(v0, v1);
                *(__half2*)(g_hb + (size_t)r1 * HIDDEN + col) = __float22half2_rn(make_float2(v0, v1));
            }
        }
}

// ---------------- per-graph mean of current g_h -> g_gmean[:, l*256 .. ] ----------------
__global__ void readout_layer_kernel(int l, int N) {
    int g = blockIdx.x;
    int c = threadIdx.x;
    int beg = clampi(g_gstart[g], 0, N);
    int end = clampi(g_gstart[g + 1], beg, N);
    float a = 0.f;
    for (int r = beg; r < end; r++)
        a += g_h[(size_t)r * HIDDEN + c];
    g_gmean[(size_t)g * CAT + l * HIDDEN + c] = a * g_ginv[g];
}

// ---------------- final tiny GEMM: out[512,256] = g_gmean @ W_out + b_out ----------------
__global__ void gemm_out_kernel(const float* __restrict__ W,
                                const float* __restrict__ b,
                                float* __restrict__ out) {
    __shared__ float sa[8][CAT];
    int g0 = blockIdx.x * 8;
    int tid = threadIdx.x;
    for (int i = tid; i < 8 * CAT; i += blockDim.x) {
        int r = i / CAT, k = i % CAT;
        sa[r][k] = g_gmean[(size_t)(g0 + r) * CAT + k];
    }
    __syncthreads();
    int c = tid;
    float acc[8];
    float bc = b[c];
#pragma unroll
    for (int r = 0; r < 8; r++) acc[r] = bc;
    for (int k = 0; k < CAT; k++) {
        float w = W[k * HIDDEN + c];
#pragma unroll
        for (int r = 0; r < 8; r++) acc[r] = fmaf(sa[r][k], w, acc[r]);
    }
#pragma unroll
    for (int r = 0; r < 8; r++)
        out[(size_t)(g0 + r) * HIDDEN + c] = acc[r];
}

// ---------------- launch ----------------
extern "C" void kernel_launch(void* const* d_in, const int* in_sizes, int n_in,
                              void* d_out, int out_size) {
    int ix_h = 0, ix_src = 1, ix_dst = 2, ix_gid = 3;
    int ix_Wp = 4, ix_bp = 5, ix_Wl = 6, ix_bl = 7, ix_Wo = 8, ix_bo = 9;

    if (n_in == 10) {
        int ih = -1, ig = -1, iwp = -1, iwl = -1, iwo = -1;
        int pair[2] = {-1, -1}; int pc = 0;
        int bias3[3] = {-1, -1, -1}; int bc = 0;
        bool ok = true;
        for (int i = 0; i < 10; i++) {
            int s = in_sizes[i];
            if      (s == N_NODES * IN_SIZE)  ih = i;
            else if (s == N_EDGES)            { if (pc < 2) pair[pc++] = i; else ok = false; }
            else if (s == N_NODES)            ig = i;
            else if (s == IN_SIZE * HIDDEN)   iwp = i;
            else if (s == HIDDEN * HIDDEN)    iwl = i;
            else if (s == CAT * HIDDEN)       iwo = i;
            else if (s == HIDDEN)             { if (bc < 3) bias3[bc++] = i; else ok = false; }
            else ok = false;
        }
        if (ok && ih >= 0 && ig >= 0 && iwp >= 0 && iwl >= 0 && iwo >= 0 && pc == 2 && bc == 3) {
            ix_h = ih; ix_src = pair[0]; ix_dst = pair[1]; ix_gid = ig;
            ix_Wp = iwp; ix_bp = bias3[0]; ix_Wl = iwl; ix_bl = bias3[1];
            ix_Wo = iwo; ix_bo = bias3[2];
        }
    }

    const float* h_in   = (const float*)d_in[ix_h];
    const int*   src    = (const int*)d_in[ix_src];
    const int*   dst    = (const int*)d_in[ix_dst];
    const int*   gid    = (const int*)d_in[ix_gid];
    const float* W_proj = (const float*)d_in[ix_Wp];
    const float* b_proj = (const float*)d_in[ix_bp];
    const float* W_lin  = (const float*)d_in[ix_Wl];
    const float* b_lin  = (const float*)d_in[ix_bl];
    const float* W_out  = (const float*)d_in[ix_Wo];
    const float* b_out  = (const float*)d_in[ix_bo];
    float* out = (float*)d_out;

    const int E = N_EDGES;
    const int N = N_NODES;
    const int SCAN_BLOCKS = (N + 1023) / 1024;

    zero_kernel<<<(N + 255) / 256, 256>>>(N);
    hist_all_kernel<<<(E + 255) / 256, 256>>>(dst, gid, E, N);
    scan_pass1_kernel<<<SCAN_BLOCKS, 1024>>>(N);
    scan_mid_kernel<<<2, 64>>>(SCAN_BLOCKS, N);
    scan_pass3_kernel<<<SCAN_BLOCKS, 1024>>>(N);
    scatter_kernel<<<(E + 255) / 256, 256>>>(src, dst, E);
    splitW_kernel<<<(HIDDEN * HIDDEN + 255) / 256, 256>>>(W_lin, HIDDEN * HIDDEN);
    proj_kernel<<<(N + 7) / 8, 256>>>(h_in, W_proj, b_proj, N);

    dim3 ggrid((N + 127) / 128, HIDDEN / 64);
    int agg_blocks = (N + 7) / 8;
    for (int l = 0; l < CONVS; l++) {
        agg_kernel<<<agg_blocks, 256>>>(N, E);
        gemm_mma_kernel<<<ggrid, 256>>>(b_lin, N);
        readout_layer_kernel<<<N_GRAPHS, 256>>>(l, N);
    }

    gemm_out_kernel<<<N_GRAPHS / 8, 256>>>(W_out, b_out, out);
}